// round 9
// baseline (speedup 1.0000x reference)
#include <cuda_runtime.h>

// Problem constants
#define NG   40      // groups
#define CPG  8       // channels per group (320/40)
#define ND   48      // disparity bins
#define NH   128
#define NW   240
#define NCC  12      // concat channels per tensor
#define PAD  48      // left zero-pad for shifted tgt (>= max d)
#define TROW (NW + PAD)   // 288 floats per padded tgt row
#define HW   (NH * NW)

// ---------------------------------------------------------------------------
// Kernel 1: groupwise-correlation volume. One block per (g, h-PAIR),
// 192 threads, 180 active = 60 w-quads x 3 d-quad groups.
// 4w x 4d register tile, k-loop of 4: d0 = (dgrp + 3k)*4 covers all 12
// d-quads. acc[4][4] (16 regs) + 8-float window keeps natural register use
// ~60-68 -> 5 blocks/SM (~47% occ) WITHOUT a forced cap (R7 showed caps
// spill). LDS/out rises 16->24 B (had headroom: L1 was 44.9% at 26% occ).
// ref pre-scaled by 1/8 in the smem fill; h-pair keeps fill/stores as
// 1920-B contiguous runs and halves per-block fixed overhead.
// ---------------------------------------------------------------------------
__global__ __launch_bounds__(192) void gwc_kernel(const float* __restrict__ ref,
                                                  const float* __restrict__ tgt,
                                                  float* __restrict__ out) {
    // layout: sref[c][hh][w] (480 floats/c), stgt[c][hh][TROW] (576 floats/c)
    __shared__ __align__(16) float sref[CPG * 2 * NW];    // 3840 floats
    __shared__ __align__(16) float stgt[CPG * 2 * TROW];  // 4608 floats

    const int g   = blockIdx.x;        // 0..39
    const int hp  = blockIdx.y;        // 0..63
    const int h   = hp * 2;
    const int tid = threadIdx.x;

    const float* gref = ref + ((size_t)(g * CPG) * NH + h) * NW;
    const float* gtgt = tgt + ((size_t)(g * CPG) * NH + h) * NW;

    // Fill: rows h and h+1 are contiguous (480 floats per channel).
    for (int i = tid; i < CPG * 120; i += 192) {           // ref, pre-scaled
        int c = i / 120, j = i % 120;
        float4 v = *(const float4*)(gref + (size_t)c * HW + j * 4);
        v.x *= 0.125f; v.y *= 0.125f; v.z *= 0.125f; v.w *= 0.125f;
        *(float4*)(sref + c * 480 + j * 4) = v;
    }
    {                                                      // zero pads
        int i = tid;                    // CPG*2*12 = 192 float4 pads
        int c = i / 24, rem = i % 24, hh = rem / 12, pq = rem % 12;
        *(float4*)(stgt + c * 576 + hh * TROW + pq * 4) =
            make_float4(0.f, 0.f, 0.f, 0.f);
    }
    for (int i = tid; i < CPG * 120; i += 192) {           // tgt
        int c = i / 120, j = i % 120;
        int hh = j / 60, wq = j % 60;
        float4 v = *(const float4*)(gtgt + (size_t)c * HW + j * 4);
        *(float4*)(stgt + c * 576 + hh * TROW + PAD + wq * 4) = v;
    }
    __syncthreads();

    const int wq   = tid & 63;    // 0..59 active per 64-thread slice
    const int dgrp = tid >> 6;    // 0..2
    if (wq >= NW / 4) return;
    const int w0 = wq * 4;

#pragma unroll
    for (int hh = 0; hh < 2; hh++) {
        float* outb = out + (size_t)g * ND * HW + (size_t)(h + hh) * NW + w0;
        const float* srb = sref + hh * NW + w0;
        const float* stb = stgt + hh * TROW + PAD + w0;

#pragma unroll
        for (int k = 0; k < 4; k++) {
            const int d0 = (dgrp + 3 * k) * 4;   // d-quads 0..11 -> all 48 d
            float acc[4][4] = {};
#pragma unroll
            for (int c = 0; c < CPG; c++) {
                // ref quad for this channel (pre-scaled by 1/8)
                float4 rv = *(const float4*)(srb + c * 480);
                float rr[4] = {rv.x, rv.y, rv.z, rv.w};
                // window tgt[w0-d0-4 .. w0-d0+3], 16B-aligned
                const float* tp = stb + c * 576 - d0 - 4;
                float4 v0 = *(const float4*)tp;
                float4 v1 = *(const float4*)(tp + 4);
                float wv[8] = {v0.x, v0.y, v0.z, v0.w,
                               v1.x, v1.y, v1.z, v1.w};
#pragma unroll
                for (int j = 0; j < 4; j++)
#pragma unroll
                    for (int i = 0; i < 4; i++)
                        acc[j][i] += rr[i] * wv[i + 4 - j];  // tgt[w0+i-(d0+j)]
            }
#pragma unroll
            for (int j = 0; j < 4; j++) {
                float4 o = make_float4(acc[j][0], acc[j][1],
                                       acc[j][2], acc[j][3]);
                *(float4*)(outb + (size_t)(d0 + j) * HW) = o;
            }
        }
    }
}

// ---------------------------------------------------------------------------
// Kernel 2: concat volume. One block per (c_out, d); d uniform per block.
// Thread = (w-quad, h-lane); h-loop by pointer increment (no divides).
// Shift misalignment s = d&3 compile-time specialized; masks precomputed.
// ---------------------------------------------------------------------------
template <int S>
__device__ __forceinline__ float4 shift_sel(float4 lo, float4 hi) {
    if (S == 0) return hi;
    if (S == 1) return make_float4(lo.w, hi.x, hi.y, hi.z);
    if (S == 2) return make_float4(lo.z, lo.w, hi.x, hi.y);
    return make_float4(lo.y, lo.z, lo.w, hi.x);
}

template <int S>
__device__ __forceinline__ void tgt_loop(const float* __restrict__ p, int o0, int o1,
                                         float* __restrict__ ob, int hy,
                                         bool k0, bool k1, bool k2, bool k3) {
#pragma unroll 4
    for (int h = hy; h < NH; h += 4) {
        float4 lo = (S != 0) ? *(const float4*)(p + (size_t)h * NW + o0)
                             : make_float4(0.f, 0.f, 0.f, 0.f);
        float4 hi = *(const float4*)(p + (size_t)h * NW + o1);
        float4 o = shift_sel<S>(lo, hi);
        o.x = k0 ? o.x : 0.f;
        o.y = k1 ? o.y : 0.f;
        o.z = k2 ? o.z : 0.f;
        o.w = k3 ? o.w : 0.f;
        *(float4*)(ob + (size_t)h * NW) = o;
    }
}

__global__ __launch_bounds__(256) void concat_kernel(const float* __restrict__ refc,
                                                     const float* __restrict__ tgtc,
                                                     float* __restrict__ out) {
    const int c   = blockIdx.x / ND;   // 0..23
    const int d   = blockIdx.x % ND;   // uniform per block
    const int tid = threadIdx.x;
    const int wq  = tid & 63;          // 0..59 active
    const int hy  = tid >> 6;          // 0..3
    if (wq >= NW / 4) return;
    const int w0 = wq * 4;

    const bool k0 = (w0 + 0 >= d), k1 = (w0 + 1 >= d),
               k2 = (w0 + 2 >= d), k3 = (w0 + 3 >= d);

    float* ob = out + ((size_t)(NG + c) * ND + d) * HW + w0;

    if (c < NCC) {
        const float* p = refc + (size_t)c * HW + w0;
#pragma unroll 4
        for (int h = hy; h < NH; h += 4) {
            float4 v = *(const float4*)(p + (size_t)h * NW);
            v.x = k0 ? v.x : 0.f;
            v.y = k1 ? v.y : 0.f;
            v.z = k2 ? v.z : 0.f;
            v.w = k3 ? v.w : 0.f;
            *(float4*)(ob + (size_t)h * NW) = v;
        }
    } else {
        const int s   = d & 3;
        const int dlo = d - s;
        const float* p = tgtc + (size_t)(c - NCC) * HW;
        const int a0 = w0 - dlo - 4;
        const int o0 = a0 < 0 ? 0 : a0;          // clamped aligned bases
        const int o1 = a0 + 4 < 0 ? 0 : a0 + 4;
        switch (s) {
            case 0:  tgt_loop<0>(p, o0, o1, ob, hy, k0, k1, k2, k3); break;
            case 1:  tgt_loop<1>(p, o0, o1, ob, hy, k0, k1, k2, k3); break;
            case 2:  tgt_loop<2>(p, o0, o1, ob, hy, k0, k1, k2, k3); break;
            default: tgt_loop<3>(p, o0, o1, ob, hy, k0, k1, k2, k3); break;
        }
    }
}

// ---------------------------------------------------------------------------
extern "C" void kernel_launch(void* const* d_in, const int* in_sizes, int n_in,
                              void* d_out, int out_size) {
    (void)in_sizes; (void)n_in; (void)out_size;
    const float* ref_gwc = (const float*)d_in[0];
    const float* tgt_gwc = (const float*)d_in[1];
    const float* ref_c   = (const float*)d_in[2];
    const float* tgt_c   = (const float*)d_in[3];
    float* out = (float*)d_out;

    // concat first so ncu -s 5 -c 1 keeps landing on gwc_kernel.
    concat_kernel<<<2 * NCC * ND, 256>>>(ref_c, tgt_c, out);
    gwc_kernel<<<dim3(NG, NH / 2), 192>>>(ref_gwc, tgt_gwc, out);
}

// round 11
// speedup vs baseline: 1.2555x; 1.2555x over previous
#include <cuda_runtime.h>
#include <cstdint>

// Problem constants
#define NG   40      // groups
#define CPG  8       // channels per group (320/40)
#define ND   48      // disparity bins
#define NH   128
#define NW   240
#define NCC  12      // concat channels per tensor
#define PAD  48      // left zero-pad for shifted tgt (>= max d)
#define TROW (NW + PAD)   // 288 floats per padded tgt row
#define HW   (NH * NW)

#define NTILES   (NG * NH)         // 5120 (g,h) tiles
#define GWC_GRID 608               // ~4 CTAs/SM, all resident (persistent)
#define BUF_FLT  (CPG * NW + CPG * TROW)   // 4224 floats per buffer

// -------------------- cp.async helpers --------------------
__device__ __forceinline__ void cp_async16(void* smem_dst, const void* gmem_src) {
    uint32_t s = (uint32_t)__cvta_generic_to_shared(smem_dst);
    asm volatile("cp.async.cg.shared.global [%0], [%1], 16;\n" ::
                 "r"(s), "l"(gmem_src));
}
__device__ __forceinline__ void cp_commit() {
    asm volatile("cp.async.commit_group;\n");
}
template <int N>
__device__ __forceinline__ void cp_wait() {
    asm volatile("cp.async.wait_group %0;\n" :: "n"(N));
}

// ---------------------------------------------------------------------------
// Kernel 1: groupwise-correlation volume — persistent CTAs, double-buffered
// cp.async pipeline over (g, h) tiles. Compute core = R9's 4w x 4d x k=4
// register tile (73 regs, proven). While tile i is computed from buf[p],
// tile i+1 streams into buf[p^1]; fill latency (577-cyc LDG) is hidden
// behind ~5k cycles of compute instead of being exposed per tile.
// 1/8 group-mean scale applied in the store epilogue (1 FMUL/output).
// ---------------------------------------------------------------------------
__global__ __launch_bounds__(192) void gwc_kernel(const float* __restrict__ ref,
                                                  const float* __restrict__ tgt,
                                                  float* __restrict__ out) {
    // per buffer: sref = [0,1920), stgt = [1920, 1920+2304) (padded rows)
    __shared__ __align__(16) float sbuf[2][BUF_FLT];

    const int tid = threadIdx.x;

    // Zero the pad regions of both buffers once (fills never touch them).
    for (int b = 0; b < 2; b++)
        for (int i = tid; i < CPG * (PAD / 4); i += 192) {
            int c = i / (PAD / 4), pq = i % (PAD / 4);
            *(float4*)(&sbuf[b][CPG * NW + c * TROW + pq * 4]) =
                make_float4(0.f, 0.f, 0.f, 0.f);
        }

    const int stride = gridDim.x;
    int t = blockIdx.x;

    // Fill lambda: tile t -> buffer buf (ref 480 f4 + tgt 480 f4, cp.async)
    auto fill = [&](float* buf, int tt) {
        const int g = tt / NH, h = tt % NH;
        const float* gr = ref + ((size_t)(g * CPG) * NH + h) * NW;
        const float* gt = tgt + ((size_t)(g * CPG) * NH + h) * NW;
        float* sr = buf;
        float* st = buf + CPG * NW;
        for (int i = tid; i < CPG * 60; i += 192) {
            int c = i / 60, wq = i % 60;
            cp_async16(sr + c * NW + wq * 4,        gr + (size_t)c * HW + wq * 4);
            cp_async16(st + c * TROW + PAD + wq * 4, gt + (size_t)c * HW + wq * 4);
        }
    };

    // Prologue: start fill of first tile.
    if (t < NTILES) fill(sbuf[0], t);
    cp_commit();

    const int wq   = tid & 63;    // 0..59 active per 64-thread slice
    const int dgrp = tid >> 6;    // 0..2
    const bool active = (wq < NW / 4);
    const int w0 = wq * 4;

    int p = 0;
    for (; t < NTILES; t += stride) {
        const int tn = t + stride;
        if (tn < NTILES) {            // stream next tile into the other buffer
            fill(sbuf[p ^ 1], tn);
            cp_commit();
            cp_wait<1>();             // current tile's fill complete
        } else {
            cp_wait<0>();
        }
        __syncthreads();              // fills visible to all threads

        if (active) {
            const int g = t / NH, h = t % NH;
            const float* srb = sbuf[p] + w0;                      // sref base
            const float* stb = sbuf[p] + CPG * NW + PAD + w0;     // stgt base
            float* outb = out + (size_t)g * ND * HW + (size_t)h * NW + w0;

#pragma unroll
            for (int k = 0; k < 4; k++) {
                const int d0 = (dgrp + 3 * k) * 4;  // d-quads 0..11 -> 48 d
                float acc[4][4] = {};
#pragma unroll
                for (int c = 0; c < CPG; c++) {
                    float4 rv = *(const float4*)(srb + c * NW);
                    float rr[4] = {rv.x, rv.y, rv.z, rv.w};
                    // window tgt[w0-d0-4 .. w0-d0+3], 16B-aligned
                    const float* tp = stb + c * TROW - d0 - 4;
                    float4 v0 = *(const float4*)tp;
                    float4 v1 = *(const float4*)(tp + 4);
                    float wv[8] = {v0.x, v0.y, v0.z, v0.w,
                                   v1.x, v1.y, v1.z, v1.w};
#pragma unroll
                    for (int j = 0; j < 4; j++)
#pragma unroll
                        for (int i = 0; i < 4; i++)
                            acc[j][i] += rr[i] * wv[i + 4 - j];
                }
#pragma unroll
                for (int j = 0; j < 4; j++) {
                    float4 o = make_float4(acc[j][0] * 0.125f,
                                           acc[j][1] * 0.125f,
                                           acc[j][2] * 0.125f,
                                           acc[j][3] * 0.125f);
                    *(float4*)(outb + (size_t)(d0 + j) * HW) = o;
                }
            }
        }
        __syncthreads();              // reads done before buffer is refilled
        p ^= 1;
    }
}

// ---------------------------------------------------------------------------
// Kernel 2: concat volume. One block per (c_out, d); d uniform per block.
// Thread = (w-quad, h-lane); h-loop by pointer increment (no divides).
// Shift misalignment s = d&3 compile-time specialized; masks precomputed.
// ---------------------------------------------------------------------------
template <int S>
__device__ __forceinline__ float4 shift_sel(float4 lo, float4 hi) {
    if (S == 0) return hi;
    if (S == 1) return make_float4(lo.w, hi.x, hi.y, hi.z);
    if (S == 2) return make_float4(lo.z, lo.w, hi.x, hi.y);
    return make_float4(lo.y, lo.z, lo.w, hi.x);
}

template <int S>
__device__ __forceinline__ void tgt_loop(const float* __restrict__ p, int o0, int o1,
                                         float* __restrict__ ob, int hy,
                                         bool k0, bool k1, bool k2, bool k3) {
#pragma unroll 4
    for (int h = hy; h < NH; h += 4) {
        float4 lo = (S != 0) ? *(const float4*)(p + (size_t)h * NW + o0)
                             : make_float4(0.f, 0.f, 0.f, 0.f);
        float4 hi = *(const float4*)(p + (size_t)h * NW + o1);
        float4 o = shift_sel<S>(lo, hi);
        o.x = k0 ? o.x : 0.f;
        o.y = k1 ? o.y : 0.f;
        o.z = k2 ? o.z : 0.f;
        o.w = k3 ? o.w : 0.f;
        *(float4*)(ob + (size_t)h * NW) = o;
    }
}

__global__ __launch_bounds__(256) void concat_kernel(const float* __restrict__ refc,
                                                     const float* __restrict__ tgtc,
                                                     float* __restrict__ out) {
    const int c   = blockIdx.x / ND;   // 0..23
    const int d   = blockIdx.x % ND;   // uniform per block
    const int tid = threadIdx.x;
    const int wq  = tid & 63;          // 0..59 active
    const int hy  = tid >> 6;          // 0..3
    if (wq >= NW / 4) return;
    const int w0 = wq * 4;

    const bool k0 = (w0 + 0 >= d), k1 = (w0 + 1 >= d),
               k2 = (w0 + 2 >= d), k3 = (w0 + 3 >= d);

    float* ob = out + ((size_t)(NG + c) * ND + d) * HW + w0;

    if (c < NCC) {
        const float* p = refc + (size_t)c * HW + w0;
#pragma unroll 4
        for (int h = hy; h < NH; h += 4) {
            float4 v = *(const float4*)(p + (size_t)h * NW);
            v.x = k0 ? v.x : 0.f;
            v.y = k1 ? v.y : 0.f;
            v.z = k2 ? v.z : 0.f;
            v.w = k3 ? v.w : 0.f;
            *(float4*)(ob + (size_t)h * NW) = v;
        }
    } else {
        const int s   = d & 3;
        const int dlo = d - s;
        const float* p = tgtc + (size_t)(c - NCC) * HW;
        const int a0 = w0 - dlo - 4;
        const int o0 = a0 < 0 ? 0 : a0;          // clamped aligned bases
        const int o1 = a0 + 4 < 0 ? 0 : a0 + 4;
        switch (s) {
            case 0:  tgt_loop<0>(p, o0, o1, ob, hy, k0, k1, k2, k3); break;
            case 1:  tgt_loop<1>(p, o0, o1, ob, hy, k0, k1, k2, k3); break;
            case 2:  tgt_loop<2>(p, o0, o1, ob, hy, k0, k1, k2, k3); break;
            default: tgt_loop<3>(p, o0, o1, ob, hy, k0, k1, k2, k3); break;
        }
    }
}

// ---------------------------------------------------------------------------
extern "C" void kernel_launch(void* const* d_in, const int* in_sizes, int n_in,
                              void* d_out, int out_size) {
    (void)in_sizes; (void)n_in; (void)out_size;
    const float* ref_gwc = (const float*)d_in[0];
    const float* tgt_gwc = (const float*)d_in[1];
    const float* ref_c   = (const float*)d_in[2];
    const float* tgt_c   = (const float*)d_in[3];
    float* out = (float*)d_out;

    // concat first so ncu -s 5 -c 1 keeps landing on gwc_kernel.
    concat_kernel<<<2 * NCC * ND, 256>>>(ref_c, tgt_c, out);
    gwc_kernel<<<GWC_GRID, 192>>>(ref_gwc, tgt_gwc, out);
}